// round 1
// baseline (speedup 1.0000x reference)
#include <cuda_runtime.h>

// Problem dims (fixed)
#define B_   2
#define S_   2048
#define D_   1024
#define H_   16
#define KS_  64
#define NKH_ (KS_ * H_)   // 1024
#define NBH_ (B_ * H_)    // 32

// Device scratch (allocation-free rule: device globals)
__device__ float g_q[NBH_ * S_ * KS_];      // [b,h,s,k]
__device__ float g_k[NBH_ * S_ * KS_];
__device__ float g_v[NBH_ * S_ * KS_];
__device__ float g_heads[B_ * S_ * NKH_];   // [b,s, k*H+h]

// ---------------------------------------------------------------------------
// Kernel 1: QKV projection GEMM.
// C[4096][1024] = X[4096][1024] * W[1024][1024], W col index n = k*H + h.
// BM=128, BN=128, BK=8, 256 threads, 8x8 per thread.
// Epilogue writes transposed layout [b,h,s,k] for coalesced attention reads.
// ---------------------------------------------------------------------------
__global__ __launch_bounds__(256) void qkv_gemm(
    const float* __restrict__ x,
    const float* __restrict__ Wq,
    const float* __restrict__ Wk,
    const float* __restrict__ Wv)
{
    __shared__ float As[8][132];   // padded: conflict-free transposed stores
    __shared__ float Bs[8][128];

    const int bz = blockIdx.z;
    const float* W = (bz == 0) ? Wq : (bz == 1 ? Wk : Wv);
    float* O = (bz == 0) ? g_q : (bz == 1 ? g_k : g_v);

    const int row0 = blockIdx.x * 128;
    const int col0 = blockIdx.y * 128;
    const int tid  = threadIdx.x;
    const int tx   = tid & 15;
    const int ty   = tid >> 4;

    const int ar = tid >> 1;          // 0..127 (A tile row)
    const int ak = (tid & 1) * 4;     // 0 or 4 (A tile k offset)
    const int br = tid >> 5;          // 0..7   (B tile k row)
    const int bc = (tid & 31) * 4;    // 0..124 (B tile col)

    float acc[8][8];
    #pragma unroll
    for (int i = 0; i < 8; i++)
        #pragma unroll
        for (int j = 0; j < 8; j++) acc[i][j] = 0.f;

    for (int k0 = 0; k0 < D_; k0 += 8) {
        float4 av = *(const float4*)(x + (size_t)(row0 + ar) * D_ + k0 + ak);
        float4 bv = *(const float4*)(W + (size_t)(k0 + br) * NKH_ + col0 + bc);
        __syncthreads();
        As[ak + 0][ar] = av.x;
        As[ak + 1][ar] = av.y;
        As[ak + 2][ar] = av.z;
        As[ak + 3][ar] = av.w;
        *(float4*)&Bs[br][bc] = bv;
        __syncthreads();

        #pragma unroll
        for (int kk = 0; kk < 8; kk++) {
            float a[8], b[8];
            #pragma unroll
            for (int i = 0; i < 8; i++) a[i] = As[kk][ty * 8 + i];
            #pragma unroll
            for (int j = 0; j < 8; j++) b[j] = Bs[kk][tx * 8 + j];
            #pragma unroll
            for (int i = 0; i < 8; i++)
                #pragma unroll
                for (int j = 0; j < 8; j++)
                    acc[i][j] = fmaf(a[i], b[j], acc[i][j]);
        }
    }

    // Epilogue: transpose to [b,h,s,k]
    #pragma unroll
    for (int i = 0; i < 8; i++) {
        const int r  = row0 + ty * 8 + i;
        const int bb = r >> 11;          // / S_
        const int s  = r & (S_ - 1);
        #pragma unroll
        for (int j = 0; j < 8; j++) {
            const int c = col0 + tx * 8 + j;
            const int k = c >> 4;        // / H_
            const int h = c & (H_ - 1);
            O[((size_t)((bb * H_ + h) * S_ + s)) * KS_ + k] = acc[i][j];
        }
    }
}

// ---------------------------------------------------------------------------
// Kernel 2: causal flash attention per (b,h).
// 128 queries / block, 1 query row per thread (q[64], acc[64] in registers).
// Streams 32-key K/V tiles through smem; online softmax in 8-key chunks.
// ---------------------------------------------------------------------------
__global__ __launch_bounds__(128) void attn_kernel()
{
    __shared__ float Ks[32][KS_];   // 8 KB
    __shared__ float Vs[32][KS_];   // 8 KB

    const int bh = blockIdx.y;            // 0..31
    const int i0 = blockIdx.x * 128;
    const int t  = threadIdx.x;
    const int i  = i0 + t;                // this thread's query row

    const float* qb = g_q + (size_t)bh * S_ * KS_;
    const float* kb = g_k + (size_t)bh * S_ * KS_;
    const float* vb = g_v + (size_t)bh * S_ * KS_;

    float q[KS_];
    #pragma unroll
    for (int d = 0; d < KS_; d += 4) {
        float4 v4 = *(const float4*)(qb + (size_t)i * KS_ + d);
        q[d + 0] = v4.x * 0.125f;   // fold 1/sqrt(64)
        q[d + 1] = v4.y * 0.125f;
        q[d + 2] = v4.z * 0.125f;
        q[d + 3] = v4.w * 0.125f;
    }

    float acc[KS_];
    #pragma unroll
    for (int d = 0; d < KS_; d++) acc[d] = 0.f;
    float m = -1e30f, l = 0.f;

    const int jmax = i0 + 128;   // causal: keys beyond the query tile never needed
    for (int j0 = 0; j0 < jmax; j0 += 32) {
        __syncthreads();
        #pragma unroll
        for (int u = 0; u < 4; u++) {
            const int idx = t + u * 128;   // float4 index, 512 total
            ((float4*)Ks)[idx] = ((const float4*)(kb + (size_t)j0 * KS_))[idx];
            ((float4*)Vs)[idx] = ((const float4*)(vb + (size_t)j0 * KS_))[idx];
        }
        __syncthreads();

        #pragma unroll 1
        for (int jc = 0; jc < 32; jc += 8) {
            float sc[8];
            #pragma unroll
            for (int u = 0; u < 8; u++) {
                float s = 0.f;
                #pragma unroll
                for (int d = 0; d < KS_; d++)
                    s = fmaf(q[d], Ks[jc + u][d], s);
                sc[u] = s;
            }
            // causal mask (strictly-future keys)
            if (j0 + jc + 7 > i) {
                #pragma unroll
                for (int u = 0; u < 8; u++)
                    if (j0 + jc + u > i) sc[u] = -1e30f;
            }
            float mt = m;
            #pragma unroll
            for (int u = 0; u < 8; u++) mt = fmaxf(mt, sc[u]);
            const float corr = __expf(m - mt);
            m = mt;
            l *= corr;
            #pragma unroll
            for (int d = 0; d < KS_; d++) acc[d] *= corr;
            #pragma unroll
            for (int u = 0; u < 8; u++) {
                sc[u] = __expf(sc[u] - mt);
                l += sc[u];
            }
            #pragma unroll
            for (int u = 0; u < 8; u++)
                #pragma unroll
                for (int d = 0; d < KS_; d++)
                    acc[d] = fmaf(sc[u], Vs[jc + u][d], acc[d]);
        }
    }

    const float inv = 1.f / l;
    const int bb = bh >> 4;       // / H_
    const int h  = bh & (H_ - 1);
    float* op = g_heads + ((size_t)(bb * S_ + i)) * NKH_ + h;
    #pragma unroll
    for (int k2 = 0; k2 < KS_; k2++)
        op[k2 * H_] = acc[k2] * inv;
}

// ---------------------------------------------------------------------------
// Kernel 3: output projection.
// out[4096][64] = heads[4096][1024] @ kernel[1024][64].
// BM=32, BN=64, BK=32, 256 threads, 2x4 per thread. Grid = 128 blocks.
// ---------------------------------------------------------------------------
__global__ __launch_bounds__(256) void out_gemm(
    const float* __restrict__ kern,
    float* __restrict__ out)
{
    __shared__ float Hs[32][33];   // transposed heads tile, padded
    __shared__ float Ws[32][64];

    const int row0 = blockIdx.x * 32;
    const int tid  = threadIdx.x;
    const int tx   = tid & 15;     // col group (4 cols)
    const int ty   = tid >> 4;     // row group (2 rows)

    const int hr = tid >> 3;           // 0..31 heads row
    const int hc = (tid & 7) * 4;      // 0..28 heads k offset
    const int wr = tid >> 4;           // 0..15 kernel k row
    const int wc = (tid & 15) * 4;     // 0..60 kernel col

    float acc[2][4];
    #pragma unroll
    for (int ii = 0; ii < 2; ii++)
        #pragma unroll
        for (int jj = 0; jj < 4; jj++) acc[ii][jj] = 0.f;

    for (int k0 = 0; k0 < NKH_; k0 += 32) {
        float4 hv = *(const float4*)(g_heads + (size_t)(row0 + hr) * NKH_ + k0 + hc);
        float4 w0 = *(const float4*)(kern + (size_t)(k0 + wr) * KS_ + wc);
        float4 w1 = *(const float4*)(kern + (size_t)(k0 + wr + 16) * KS_ + wc);
        __syncthreads();
        Hs[hc + 0][hr] = hv.x;
        Hs[hc + 1][hr] = hv.y;
        Hs[hc + 2][hr] = hv.z;
        Hs[hc + 3][hr] = hv.w;
        *(float4*)&Ws[wr][wc]      = w0;
        *(float4*)&Ws[wr + 16][wc] = w1;
        __syncthreads();

        #pragma unroll
        for (int kk = 0; kk < 32; kk++) {
            const float a0 = Hs[kk][ty * 2 + 0];
            const float a1 = Hs[kk][ty * 2 + 1];
            const float b0 = Ws[kk][tx * 4 + 0];
            const float b1 = Ws[kk][tx * 4 + 1];
            const float b2 = Ws[kk][tx * 4 + 2];
            const float b3 = Ws[kk][tx * 4 + 3];
            acc[0][0] = fmaf(a0, b0, acc[0][0]);
            acc[0][1] = fmaf(a0, b1, acc[0][1]);
            acc[0][2] = fmaf(a0, b2, acc[0][2]);
            acc[0][3] = fmaf(a0, b3, acc[0][3]);
            acc[1][0] = fmaf(a1, b0, acc[1][0]);
            acc[1][1] = fmaf(a1, b1, acc[1][1]);
            acc[1][2] = fmaf(a1, b2, acc[1][2]);
            acc[1][3] = fmaf(a1, b3, acc[1][3]);
        }
    }

    #pragma unroll
    for (int ii = 0; ii < 2; ii++) {
        float4 o = make_float4(acc[ii][0], acc[ii][1], acc[ii][2], acc[ii][3]);
        *(float4*)(out + (size_t)(row0 + ty * 2 + ii) * KS_ + tx * 4) = o;
    }
}

// ---------------------------------------------------------------------------
extern "C" void kernel_launch(void* const* d_in, const int* in_sizes, int n_in,
                              void* d_out, int out_size)
{
    (void)in_sizes; (void)n_in; (void)out_size;
    const float* x  = (const float*)d_in[0];
    const float* Wq = (const float*)d_in[1];
    const float* Wk = (const float*)d_in[2];
    const float* Wv = (const float*)d_in[3];
    const float* kr = (const float*)d_in[4];
    float* out = (float*)d_out;

    dim3 g1(B_ * S_ / 128, NKH_ / 128, 3);   // (32, 8, 3)
    qkv_gemm<<<g1, 256>>>(x, Wq, Wk, Wv);

    dim3 g2(S_ / 128, NBH_);                 // (16, 32)
    attn_kernel<<<g2, 128>>>();

    out_gemm<<<B_ * S_ / 32, 256>>>(kr, out); // 128 blocks
}

// round 2
// speedup vs baseline: 1.1254x; 1.1254x over previous
#include <cuda_runtime.h>

// Problem dims (fixed)
#define B_   2
#define S_   2048
#define D_   1024
#define H_   16
#define KS_  64
#define NKH_ (KS_ * H_)   // 1024
#define NBH_ (B_ * H_)    // 32

// Device scratch (allocation-free rule: device globals)
__device__ float g_q[NBH_ * S_ * KS_];      // [b,h,s,k]
__device__ float g_k[NBH_ * S_ * KS_];
__device__ float g_v[NBH_ * S_ * KS_];
__device__ float g_heads[B_ * S_ * NKH_];   // [b,s, k*H+h]

// ---------------------------------------------------------------------------
// Kernel 1: QKV projection GEMM, double-buffered.
// C[4096][1024] = X[4096][1024] * W[1024][1024].
// BM=128, BN=128, BK=8, 256 threads, 8x8 per thread, 2 CTAs/SM.
// ---------------------------------------------------------------------------
__global__ __launch_bounds__(256, 2) void qkv_gemm(
    const float* __restrict__ x,
    const float* __restrict__ Wq,
    const float* __restrict__ Wk,
    const float* __restrict__ Wv)
{
    // 132-float rows: 528 B = 33*16 -> float4 loads stay 16B-aligned,
    // and transposed scalar stores are bank-conflict-free.
    __shared__ float As[2][8][132];
    __shared__ float Bs[2][8][128];

    const int bz = blockIdx.z;
    const float* W = (bz == 0) ? Wq : (bz == 1 ? Wk : Wv);
    float* O = (bz == 0) ? g_q : (bz == 1 ? g_k : g_v);

    const int row0 = blockIdx.x * 128;
    const int col0 = blockIdx.y * 128;
    const int tid  = threadIdx.x;
    const int tx   = tid & 15;
    const int ty   = tid >> 4;

    const int ar = tid >> 1;          // 0..127 (A tile row)
    const int ak = (tid & 1) * 4;     // 0 or 4 (A tile k offset)
    const int br = tid >> 5;          // 0..7   (B tile k row)
    const int bc = (tid & 31) * 4;    // 0..124 (B tile col)

    const float* xp = x + (size_t)(row0 + ar) * D_ + ak;
    const float* wp = W + (size_t)br * NKH_ + col0 + bc;

    float acc[8][8];
    #pragma unroll
    for (int i = 0; i < 8; i++)
        #pragma unroll
        for (int j = 0; j < 8; j++) acc[i][j] = 0.f;

    // Preload tile 0 into buffer 0
    float4 av = *(const float4*)(xp);
    float4 bv = *(const float4*)(wp);
    As[0][ak + 0][ar] = av.x;
    As[0][ak + 1][ar] = av.y;
    As[0][ak + 2][ar] = av.z;
    As[0][ak + 3][ar] = av.w;
    *(float4*)&Bs[0][br][bc] = bv;
    __syncthreads();

    int cur = 0;
    for (int k0 = 8; k0 < D_; k0 += 8) {
        // Prefetch next tile into registers (latency overlapped with compute)
        av = *(const float4*)(xp + k0);
        bv = *(const float4*)(wp + (size_t)k0 * NKH_);

        // Compute on current buffer
        #pragma unroll
        for (int kk = 0; kk < 8; kk++) {
            float4 a0 = *(const float4*)&As[cur][kk][ty * 8];
            float4 a1 = *(const float4*)&As[cur][kk][ty * 8 + 4];
            float4 b0 = *(const float4*)&Bs[cur][kk][tx * 8];
            float4 b1 = *(const float4*)&Bs[cur][kk][tx * 8 + 4];
            float a[8] = {a0.x, a0.y, a0.z, a0.w, a1.x, a1.y, a1.z, a1.w};
            float b[8] = {b0.x, b0.y, b0.z, b0.w, b1.x, b1.y, b1.z, b1.w};
            #pragma unroll
            for (int i = 0; i < 8; i++)
                #pragma unroll
                for (int j = 0; j < 8; j++)
                    acc[i][j] = fmaf(a[i], b[j], acc[i][j]);
        }

        // Stage next tile into the other buffer (safe: everyone passed the
        // previous sync, which followed their reads of this buffer)
        const int nxt = cur ^ 1;
        As[nxt][ak + 0][ar] = av.x;
        As[nxt][ak + 1][ar] = av.y;
        As[nxt][ak + 2][ar] = av.z;
        As[nxt][ak + 3][ar] = av.w;
        *(float4*)&Bs[nxt][br][bc] = bv;
        __syncthreads();
        cur = nxt;
    }

    // Final tile
    #pragma unroll
    for (int kk = 0; kk < 8; kk++) {
        float4 a0 = *(const float4*)&As[cur][kk][ty * 8];
        float4 a1 = *(const float4*)&As[cur][kk][ty * 8 + 4];
        float4 b0 = *(const float4*)&Bs[cur][kk][tx * 8];
        float4 b1 = *(const float4*)&Bs[cur][kk][tx * 8 + 4];
        float a[8] = {a0.x, a0.y, a0.z, a0.w, a1.x, a1.y, a1.z, a1.w};
        float b[8] = {b0.x, b0.y, b0.z, b0.w, b1.x, b1.y, b1.z, b1.w};
        #pragma unroll
        for (int i = 0; i < 8; i++)
            #pragma unroll
            for (int j = 0; j < 8; j++)
                acc[i][j] = fmaf(a[i], b[j], acc[i][j]);
    }

    // Epilogue: transpose to [b,h,s,k]
    #pragma unroll
    for (int i = 0; i < 8; i++) {
        const int r  = row0 + ty * 8 + i;
        const int bb = r >> 11;          // / S_
        const int s  = r & (S_ - 1);
        #pragma unroll
        for (int j = 0; j < 8; j++) {
            const int c = col0 + tx * 8 + j;
            const int k = c >> 4;        // / H_
            const int h = c & (H_ - 1);
            O[((size_t)((bb * H_ + h) * S_ + s)) * KS_ + k] = acc[i][j];
        }
    }
}

// ---------------------------------------------------------------------------
// Kernel 2: causal flash attention per (b,h).
// 128 queries / block, 1 query row per thread (q[64], acc[64] in registers).
// 32-key smem tiles, scores in 16-key register chunks, conditional rescale.
// ---------------------------------------------------------------------------
__global__ __launch_bounds__(128) void attn_kernel()
{
    __shared__ float Ks[32][KS_];   // 8 KB
    __shared__ float Vs[32][KS_];   // 8 KB

    const int bh = blockIdx.y;            // 0..31
    const int i0 = blockIdx.x * 128;
    const int t  = threadIdx.x;
    const int i  = i0 + t;                // this thread's query row

    const float* qb = g_q + (size_t)bh * S_ * KS_;
    const float* kb = g_k + (size_t)bh * S_ * KS_;
    const float* vb = g_v + (size_t)bh * S_ * KS_;

    float q[KS_];
    #pragma unroll
    for (int d = 0; d < KS_; d += 4) {
        float4 v4 = *(const float4*)(qb + (size_t)i * KS_ + d);
        q[d + 0] = v4.x * 0.125f;   // fold 1/sqrt(64)
        q[d + 1] = v4.y * 0.125f;
        q[d + 2] = v4.z * 0.125f;
        q[d + 3] = v4.w * 0.125f;
    }

    float acc[KS_];
    #pragma unroll
    for (int d = 0; d < KS_; d++) acc[d] = 0.f;
    float m = -1e30f, l = 0.f;

    const int jmax = i0 + 128;   // causal: keys beyond the query tile never needed
    for (int j0 = 0; j0 < jmax; j0 += 32) {
        __syncthreads();
        #pragma unroll
        for (int u = 0; u < 4; u++) {
            const int idx = t + u * 128;   // float4 index, 512 total
            ((float4*)Ks)[idx] = ((const float4*)(kb + (size_t)j0 * KS_))[idx];
            ((float4*)Vs)[idx] = ((const float4*)(vb + (size_t)j0 * KS_))[idx];
        }
        __syncthreads();

        #pragma unroll 1
        for (int jc = 0; jc < 32; jc += 16) {
            float sc[16];
            #pragma unroll
            for (int u = 0; u < 16; u++) {
                const float4* kr = (const float4*)(&Ks[jc + u][0]);
                float s0 = 0.f, s1 = 0.f, s2 = 0.f, s3 = 0.f;
                #pragma unroll
                for (int dd = 0; dd < 16; dd++) {
                    float4 kv = kr[dd];
                    s0 = fmaf(q[dd * 4 + 0], kv.x, s0);
                    s1 = fmaf(q[dd * 4 + 1], kv.y, s1);
                    s2 = fmaf(q[dd * 4 + 2], kv.z, s2);
                    s3 = fmaf(q[dd * 4 + 3], kv.w, s3);
                }
                sc[u] = (s0 + s1) + (s2 + s3);
            }
            // causal mask (strictly-future keys)
            if (j0 + jc + 15 > i) {
                #pragma unroll
                for (int u = 0; u < 16; u++)
                    if (j0 + jc + u > i) sc[u] = -1e30f;
            }
            float mt = m;
            #pragma unroll
            for (int u = 0; u < 16; u++) mt = fmaxf(mt, sc[u]);
            if (mt > m) {                 // rescale only when max advances
                const float corr = __expf(m - mt);
                m = mt;
                l *= corr;
                #pragma unroll
                for (int d = 0; d < KS_; d++) acc[d] *= corr;
            }
            float psum = 0.f;
            #pragma unroll
            for (int u = 0; u < 16; u++) {
                sc[u] = __expf(sc[u] - m);
                psum += sc[u];
            }
            l += psum;
            #pragma unroll
            for (int u = 0; u < 16; u++) {
                const float4* vr = (const float4*)(&Vs[jc + u][0]);
                #pragma unroll
                for (int dd = 0; dd < 16; dd++) {
                    float4 vv = vr[dd];
                    acc[dd * 4 + 0] = fmaf(sc[u], vv.x, acc[dd * 4 + 0]);
                    acc[dd * 4 + 1] = fmaf(sc[u], vv.y, acc[dd * 4 + 1]);
                    acc[dd * 4 + 2] = fmaf(sc[u], vv.z, acc[dd * 4 + 2]);
                    acc[dd * 4 + 3] = fmaf(sc[u], vv.w, acc[dd * 4 + 3]);
                }
            }
        }
    }

    const float inv = 1.f / l;
    const int bb = bh >> 4;       // / H_
    const int h  = bh & (H_ - 1);
    float* op = g_heads + ((size_t)(bb * S_ + i)) * NKH_ + h;
    #pragma unroll
    for (int k2 = 0; k2 < KS_; k2++)
        op[k2 * H_] = acc[k2] * inv;
}

// ---------------------------------------------------------------------------
// Kernel 3: output projection.
// out[4096][64] = heads[4096][1024] @ kernel[1024][64].
// BM=32, BN=64, BK=32, 256 threads, 2x4 per thread. Grid = 128 blocks.
// ---------------------------------------------------------------------------
__global__ __launch_bounds__(256) void out_gemm(
    const float* __restrict__ kern,
    float* __restrict__ out)
{
    __shared__ float Hs[32][33];   // transposed heads tile, padded
    __shared__ float Ws[32][64];

    const int row0 = blockIdx.x * 32;
    const int tid  = threadIdx.x;
    const int tx   = tid & 15;     // col group (4 cols)
    const int ty   = tid >> 4;     // row group (2 rows)

    const int hr = tid >> 3;           // 0..31 heads row
    const int hc = (tid & 7) * 4;      // 0..28 heads k offset
    const int wr = tid >> 4;           // 0..15 kernel k row
    const int wc = (tid & 15) * 4;     // 0..60 kernel col

    float acc[2][4];
    #pragma unroll
    for (int ii = 0; ii < 2; ii++)
        #pragma unroll
        for (int jj = 0; jj < 4; jj++) acc[ii][jj] = 0.f;

    for (int k0 = 0; k0 < NKH_; k0 += 32) {
        float4 hv = *(const float4*)(g_heads + (size_t)(row0 + hr) * NKH_ + k0 + hc);
        float4 w0 = *(const float4*)(kern + (size_t)(k0 + wr) * KS_ + wc);
        float4 w1 = *(const float4*)(kern + (size_t)(k0 + wr + 16) * KS_ + wc);
        __syncthreads();
        Hs[hc + 0][hr] = hv.x;
        Hs[hc + 1][hr] = hv.y;
        Hs[hc + 2][hr] = hv.z;
        Hs[hc + 3][hr] = hv.w;
        *(float4*)&Ws[wr][wc]      = w0;
        *(float4*)&Ws[wr + 16][wc] = w1;
        __syncthreads();

        #pragma unroll
        for (int kk = 0; kk < 32; kk++) {
            const float a0 = Hs[kk][ty * 2 + 0];
            const float a1 = Hs[kk][ty * 2 + 1];
            const float b0 = Ws[kk][tx * 4 + 0];
            const float b1 = Ws[kk][tx * 4 + 1];
            const float b2 = Ws[kk][tx * 4 + 2];
            const float b3 = Ws[kk][tx * 4 + 3];
            acc[0][0] = fmaf(a0, b0, acc[0][0]);
            acc[0][1] = fmaf(a0, b1, acc[0][1]);
            acc[0][2] = fmaf(a0, b2, acc[0][2]);
            acc[0][3] = fmaf(a0, b3, acc[0][3]);
            acc[1][0] = fmaf(a1, b0, acc[1][0]);
            acc[1][1] = fmaf(a1, b1, acc[1][1]);
            acc[1][2] = fmaf(a1, b2, acc[1][2]);
            acc[1][3] = fmaf(a1, b3, acc[1][3]);
        }
    }

    #pragma unroll
    for (int ii = 0; ii < 2; ii++) {
        float4 o = make_float4(acc[ii][0], acc[ii][1], acc[ii][2], acc[ii][3]);
        *(float4*)(out + (size_t)(row0 + ty * 2 + ii) * KS_ + tx * 4) = o;
    }
}

// ---------------------------------------------------------------------------
extern "C" void kernel_launch(void* const* d_in, const int* in_sizes, int n_in,
                              void* d_out, int out_size)
{
    (void)in_sizes; (void)n_in; (void)out_size;
    const float* x  = (const float*)d_in[0];
    const float* Wq = (const float*)d_in[1];
    const float* Wk = (const float*)d_in[2];
    const float* Wv = (const float*)d_in[3];
    const float* kr = (const float*)d_in[4];
    float* out = (float*)d_out;

    dim3 g1(B_ * S_ / 128, NKH_ / 128, 3);   // (32, 8, 3)
    qkv_gemm<<<g1, 256>>>(x, Wq, Wk, Wv);

    dim3 g2(S_ / 128, NBH_);                 // (16, 32)
    attn_kernel<<<g2, 128>>>();

    out_gemm<<<B_ * S_ / 32, 256>>>(kr, out); // 128 blocks
}

// round 3
// speedup vs baseline: 1.1552x; 1.0265x over previous
#include <cuda_runtime.h>

// Problem dims (fixed)
#define B_   2
#define S_   2048
#define D_   1024
#define H_   16
#define KS_  64
#define NKH_ (KS_ * H_)   // 1024
#define NBH_ (B_ * H_)    // 32

// Device scratch (allocation-free rule: device globals)
__device__ float g_q[NBH_ * S_ * KS_];      // [b,h,s,k]
__device__ float g_k[NBH_ * S_ * KS_];
__device__ float g_v[NBH_ * S_ * KS_];
__device__ float g_heads[B_ * S_ * NKH_];   // [b,s, k*H+h]

// ---------------------------------------------------------------------------
// TF32 helpers (3xTF32 split for near-fp32 accuracy on tensor cores)
// ---------------------------------------------------------------------------
__device__ __forceinline__ unsigned f2tf32(float f) {
    unsigned r;
    asm("cvt.rna.tf32.f32 %0, %1;" : "=r"(r) : "f"(f));
    return r;
}
__device__ __forceinline__ void tf32_split(float f, unsigned& hi, unsigned& lo) {
    hi = f2tf32(f);
    lo = f2tf32(f - __uint_as_float(hi));
}
__device__ __forceinline__ void mma_tf32(float* c, const unsigned* a, const unsigned* b) {
    asm volatile(
        "mma.sync.aligned.m16n8k8.row.col.f32.tf32.tf32.f32 "
        "{%0,%1,%2,%3}, {%4,%5,%6,%7}, {%8,%9}, {%0,%1,%2,%3};"
        : "+f"(c[0]), "+f"(c[1]), "+f"(c[2]), "+f"(c[3])
        : "r"(a[0]), "r"(a[1]), "r"(a[2]), "r"(a[3]), "r"(b[0]), "r"(b[1]));
}

// ---------------------------------------------------------------------------
// Kernel 1: QKV projection GEMM on tf32 tensor cores (3xTF32).
// C[4096][1024] = X[4096][1024] * W[1024][1024].
// BM=128, BN=128, BK=16, 256 threads = 8 warps (2x4), warp tile 64x32.
// Double-buffered smem with register prefetch.
// ---------------------------------------------------------------------------
__global__ __launch_bounds__(256) void qkv_gemm(
    const float* __restrict__ x,
    const float* __restrict__ Wq,
    const float* __restrict__ Wk,
    const float* __restrict__ Wv)
{
    __shared__ float As[2][16][132];   // k-major A, padded rows
    __shared__ float Bs[2][16][128];   // k-major B

    const int bz = blockIdx.z;
    const float* W = (bz == 0) ? Wq : (bz == 1 ? Wk : Wv);
    float* O = (bz == 0) ? g_q : (bz == 1 ? g_k : g_v);

    const int row0 = blockIdx.x * 128;
    const int col0 = blockIdx.y * 128;
    const int tid  = threadIdx.x;
    const int warp = tid >> 5;
    const int lane = tid & 31;
    const int wm   = (warp >> 2) * 64;   // 0 or 64
    const int wn   = (warp & 3) * 32;    // 0,32,64,96
    const int grp  = lane >> 2;          // 0..7
    const int tig  = lane & 3;           // 0..3

    // Staging indices
    const int ar = tid >> 1;            // 0..127 A row
    const int ak = (tid & 1) * 8;       // 0 or 8 A k-offset (8 floats each)
    const int br = tid >> 5;            // 0..7   B k-row (also +8)
    const int bc = (tid & 31) * 4;      // 0..124 B col

    const float* xp = x + (size_t)(row0 + ar) * D_ + ak;
    const float* wp = W + (size_t)br * NKH_ + col0 + bc;

    float acc[4][4][4];
    #pragma unroll
    for (int i = 0; i < 4; i++)
        #pragma unroll
        for (int j = 0; j < 4; j++)
            #pragma unroll
            for (int r = 0; r < 4; r++) acc[i][j][r] = 0.f;

    // Preload tile 0
    float4 a0 = *(const float4*)(xp);
    float4 a1 = *(const float4*)(xp + 4);
    float4 w0 = *(const float4*)(wp);
    float4 w1 = *(const float4*)(wp + (size_t)8 * NKH_);
    As[0][ak + 0][ar] = a0.x; As[0][ak + 1][ar] = a0.y;
    As[0][ak + 2][ar] = a0.z; As[0][ak + 3][ar] = a0.w;
    As[0][ak + 4][ar] = a1.x; As[0][ak + 5][ar] = a1.y;
    As[0][ak + 6][ar] = a1.z; As[0][ak + 7][ar] = a1.w;
    *(float4*)&Bs[0][br][bc]     = w0;
    *(float4*)&Bs[0][br + 8][bc] = w1;
    __syncthreads();

    int cur = 0;
    for (int k0 = 16; k0 <= D_; k0 += 16) {
        // Prefetch next tile into registers (skip past the end)
        if (k0 < D_) {
            a0 = *(const float4*)(xp + k0);
            a1 = *(const float4*)(xp + k0 + 4);
            w0 = *(const float4*)(wp + (size_t)k0 * NKH_);
            w1 = *(const float4*)(wp + (size_t)(k0 + 8) * NKH_);
        }

        // Compute on current buffer: two k8 atoms
        #pragma unroll
        for (int ka = 0; ka < 16; ka += 8) {
            const int kr0 = ka + tig;
            const int kr1 = kr0 + 4;
            unsigned ahi[4][4], alo[4][4], bhi[4][2], blo[4][2];
            #pragma unroll
            for (int i = 0; i < 4; i++) {
                const int m0 = wm + i * 16 + grp;
                tf32_split(As[cur][kr0][m0],     ahi[i][0], alo[i][0]);
                tf32_split(As[cur][kr0][m0 + 8], ahi[i][1], alo[i][1]);
                tf32_split(As[cur][kr1][m0],     ahi[i][2], alo[i][2]);
                tf32_split(As[cur][kr1][m0 + 8], ahi[i][3], alo[i][3]);
            }
            #pragma unroll
            for (int j = 0; j < 4; j++) {
                const int n0 = wn + j * 8 + grp;
                tf32_split(Bs[cur][kr0][n0], bhi[j][0], blo[j][0]);
                tf32_split(Bs[cur][kr1][n0], bhi[j][1], blo[j][1]);
            }
            #pragma unroll
            for (int i = 0; i < 4; i++)
                #pragma unroll
                for (int j = 0; j < 4; j++) {
                    mma_tf32(acc[i][j], ahi[i], bhi[j]);
                    mma_tf32(acc[i][j], ahi[i], blo[j]);
                    mma_tf32(acc[i][j], alo[i], bhi[j]);
                }
        }

        if (k0 < D_) {
            const int nxt = cur ^ 1;
            As[nxt][ak + 0][ar] = a0.x; As[nxt][ak + 1][ar] = a0.y;
            As[nxt][ak + 2][ar] = a0.z; As[nxt][ak + 3][ar] = a0.w;
            As[nxt][ak + 4][ar] = a1.x; As[nxt][ak + 5][ar] = a1.y;
            As[nxt][ak + 6][ar] = a1.z; As[nxt][ak + 7][ar] = a1.w;
            *(float4*)&Bs[nxt][br][bc]     = w0;
            *(float4*)&Bs[nxt][br + 8][bc] = w1;
            __syncthreads();
            cur = nxt;
        }
    }

    // Epilogue: scatter to [b,h,s,k]
    #pragma unroll
    for (int i = 0; i < 4; i++) {
        #pragma unroll
        for (int j = 0; j < 4; j++) {
            #pragma unroll
            for (int r = 0; r < 4; r++) {
                const int mrow = wm + i * 16 + grp + ((r >= 2) ? 8 : 0);
                const int ncol = wn + j * 8 + 2 * tig + (r & 1);
                const int rr = row0 + mrow;
                const int bb = rr >> 11;          // / S_
                const int s  = rr & (S_ - 1);
                const int c  = col0 + ncol;
                const int k  = c >> 4;            // / H_
                const int h  = c & (H_ - 1);
                O[((size_t)((bb * H_ + h) * S_ + s)) * KS_ + k] = acc[i][j][r];
            }
        }
    }
}

// ---------------------------------------------------------------------------
// Kernel 2: causal flash attention per (b,h).  (unchanged from R2)
// ---------------------------------------------------------------------------
__global__ __launch_bounds__(128) void attn_kernel()
{
    __shared__ float Ks[32][KS_];   // 8 KB
    __shared__ float Vs[32][KS_];   // 8 KB

    const int bh = blockIdx.y;            // 0..31
    const int i0 = blockIdx.x * 128;
    const int t  = threadIdx.x;
    const int i  = i0 + t;                // this thread's query row

    const float* qb = g_q + (size_t)bh * S_ * KS_;
    const float* kb = g_k + (size_t)bh * S_ * KS_;
    const float* vb = g_v + (size_t)bh * S_ * KS_;

    float q[KS_];
    #pragma unroll
    for (int d = 0; d < KS_; d += 4) {
        float4 v4 = *(const float4*)(qb + (size_t)i * KS_ + d);
        q[d + 0] = v4.x * 0.125f;   // fold 1/sqrt(64)
        q[d + 1] = v4.y * 0.125f;
        q[d + 2] = v4.z * 0.125f;
        q[d + 3] = v4.w * 0.125f;
    }

    float acc[KS_];
    #pragma unroll
    for (int d = 0; d < KS_; d++) acc[d] = 0.f;
    float m = -1e30f, l = 0.f;

    const int jmax = i0 + 128;   // causal: keys beyond the query tile never needed
    for (int j0 = 0; j0 < jmax; j0 += 32) {
        __syncthreads();
        #pragma unroll
        for (int u = 0; u < 4; u++) {
            const int idx = t + u * 128;   // float4 index, 512 total
            ((float4*)Ks)[idx] = ((const float4*)(kb + (size_t)j0 * KS_))[idx];
            ((float4*)Vs)[idx] = ((const float4*)(vb + (size_t)j0 * KS_))[idx];
        }
        __syncthreads();

        #pragma unroll 1
        for (int jc = 0; jc < 32; jc += 16) {
            float sc[16];
            #pragma unroll
            for (int u = 0; u < 16; u++) {
                const float4* kr = (const float4*)(&Ks[jc + u][0]);
                float s0 = 0.f, s1 = 0.f, s2 = 0.f, s3 = 0.f;
                #pragma unroll
                for (int dd = 0; dd < 16; dd++) {
                    float4 kv = kr[dd];
                    s0 = fmaf(q[dd * 4 + 0], kv.x, s0);
                    s1 = fmaf(q[dd * 4 + 1], kv.y, s1);
                    s2 = fmaf(q[dd * 4 + 2], kv.z, s2);
                    s3 = fmaf(q[dd * 4 + 3], kv.w, s3);
                }
                sc[u] = (s0 + s1) + (s2 + s3);
            }
            // causal mask (strictly-future keys)
            if (j0 + jc + 15 > i) {
                #pragma unroll
                for (int u = 0; u < 16; u++)
                    if (j0 + jc + u > i) sc[u] = -1e30f;
            }
            float mt = m;
            #pragma unroll
            for (int u = 0; u < 16; u++) mt = fmaxf(mt, sc[u]);
            if (mt > m) {                 // rescale only when max advances
                const float corr = __expf(m - mt);
                m = mt;
                l *= corr;
                #pragma unroll
                for (int d = 0; d < KS_; d++) acc[d] *= corr;
            }
            float psum = 0.f;
            #pragma unroll
            for (int u = 0; u < 16; u++) {
                sc[u] = __expf(sc[u] - m);
                psum += sc[u];
            }
            l += psum;
            #pragma unroll
            for (int u = 0; u < 16; u++) {
                const float4* vr = (const float4*)(&Vs[jc + u][0]);
                #pragma unroll
                for (int dd = 0; dd < 16; dd++) {
                    float4 vv = vr[dd];
                    acc[dd * 4 + 0] = fmaf(sc[u], vv.x, acc[dd * 4 + 0]);
                    acc[dd * 4 + 1] = fmaf(sc[u], vv.y, acc[dd * 4 + 1]);
                    acc[dd * 4 + 2] = fmaf(sc[u], vv.z, acc[dd * 4 + 2]);
                    acc[dd * 4 + 3] = fmaf(sc[u], vv.w, acc[dd * 4 + 3]);
                }
            }
        }
    }

    const float inv = 1.f / l;
    const int bb = bh >> 4;       // / H_
    const int h  = bh & (H_ - 1);
    float* op = g_heads + ((size_t)(bb * S_ + i)) * NKH_ + h;
    #pragma unroll
    for (int k2 = 0; k2 < KS_; k2++)
        op[k2 * H_] = acc[k2] * inv;
}

// ---------------------------------------------------------------------------
// Kernel 3: output projection.  (unchanged from R2)
// ---------------------------------------------------------------------------
__global__ __launch_bounds__(256) void out_gemm(
    const float* __restrict__ kern,
    float* __restrict__ out)
{
    __shared__ float Hs[32][33];   // transposed heads tile, padded
    __shared__ float Ws[32][64];

    const int row0 = blockIdx.x * 32;
    const int tid  = threadIdx.x;
    const int tx   = tid & 15;     // col group (4 cols)
    const int ty   = tid >> 4;     // row group (2 rows)

    const int hr = tid >> 3;           // 0..31 heads row
    const int hc = (tid & 7) * 4;      // 0..28 heads k offset
    const int wr = tid >> 4;           // 0..15 kernel k row
    const int wc = (tid & 15) * 4;     // 0..60 kernel col

    float acc[2][4];
    #pragma unroll
    for (int ii = 0; ii < 2; ii++)
        #pragma unroll
        for (int jj = 0; jj < 4; jj++) acc[ii][jj] = 0.f;

    for (int k0 = 0; k0 < NKH_; k0 += 32) {
        float4 hv = *(const float4*)(g_heads + (size_t)(row0 + hr) * NKH_ + k0 + hc);
        float4 w0 = *(const float4*)(kern + (size_t)(k0 + wr) * KS_ + wc);
        float4 w1 = *(const float4*)(kern + (size_t)(k0 + wr + 16) * KS_ + wc);
        __syncthreads();
        Hs[hc + 0][hr] = hv.x;
        Hs[hc + 1][hr] = hv.y;
        Hs[hc + 2][hr] = hv.z;
        Hs[hc + 3][hr] = hv.w;
        *(float4*)&Ws[wr][wc]      = w0;
        *(float4*)&Ws[wr + 16][wc] = w1;
        __syncthreads();

        #pragma unroll
        for (int kk = 0; kk < 32; kk++) {
            const float a0 = Hs[kk][ty * 2 + 0];
            const float a1 = Hs[kk][ty * 2 + 1];
            const float b0 = Ws[kk][tx * 4 + 0];
            const float b1 = Ws[kk][tx * 4 + 1];
            const float b2 = Ws[kk][tx * 4 + 2];
            const float b3 = Ws[kk][tx * 4 + 3];
            acc[0][0] = fmaf(a0, b0, acc[0][0]);
            acc[0][1] = fmaf(a0, b1, acc[0][1]);
            acc[0][2] = fmaf(a0, b2, acc[0][2]);
            acc[0][3] = fmaf(a0, b3, acc[0][3]);
            acc[1][0] = fmaf(a1, b0, acc[1][0]);
            acc[1][1] = fmaf(a1, b1, acc[1][1]);
            acc[1][2] = fmaf(a1, b2, acc[1][2]);
            acc[1][3] = fmaf(a1, b3, acc[1][3]);
        }
    }

    #pragma unroll
    for (int ii = 0; ii < 2; ii++) {
        float4 o = make_float4(acc[ii][0], acc[ii][1], acc[ii][2], acc[ii][3]);
        *(float4*)(out + (size_t)(row0 + ty * 2 + ii) * KS_ + tx * 4) = o;
    }
}

// ---------------------------------------------------------------------------
extern "C" void kernel_launch(void* const* d_in, const int* in_sizes, int n_in,
                              void* d_out, int out_size)
{
    (void)in_sizes; (void)n_in; (void)out_size;
    const float* x  = (const float*)d_in[0];
    const float* Wq = (const float*)d_in[1];
    const float* Wk = (const float*)d_in[2];
    const float* Wv = (const float*)d_in[3];
    const float* kr = (const float*)d_in[4];
    float* out = (float*)d_out;

    dim3 g1(B_ * S_ / 128, NKH_ / 128, 3);   // (32, 8, 3)
    qkv_gemm<<<g1, 256>>>(x, Wq, Wk, Wv);

    dim3 g2(S_ / 128, NBH_);                 // (16, 32)
    attn_kernel<<<g2, 128>>>();

    out_gemm<<<B_ * S_ / 32, 256>>>(kr, out); // 128 blocks
}

// round 4
// speedup vs baseline: 2.1250x; 1.8395x over previous
#include <cuda_runtime.h>

// Problem dims (fixed)
#define B_   2
#define S_   2048
#define D_   1024
#define H_   16
#define KS_  64
#define NKH_ (KS_ * H_)   // 1024
#define NBH_ (B_ * H_)    // 32

// Device scratch (allocation-free rule: device globals)
__device__ float g_q[NBH_ * S_ * KS_];      // [b,h,s,k]
__device__ float g_k[NBH_ * S_ * KS_];
__device__ float g_v[NBH_ * S_ * KS_];
__device__ float g_heads[B_ * S_ * NKH_];   // [b,s, k*H+h]

// ---------------------------------------------------------------------------
// TF32 helpers
// ---------------------------------------------------------------------------
__device__ __forceinline__ unsigned f2tf32(float f) {
    unsigned r;
    asm("cvt.rna.tf32.f32 %0, %1;" : "=r"(r) : "f"(f));
    return r;
}
__device__ __forceinline__ float tf32f(float f) {
    return __uint_as_float(f2tf32(f));
}
__device__ __forceinline__ void tf32_split(float f, unsigned& hi, unsigned& lo) {
    hi = f2tf32(f);
    lo = f2tf32(f - __uint_as_float(hi));
}
__device__ __forceinline__ void mma_tf32(float* c, const unsigned* a, const unsigned* b) {
    asm volatile(
        "mma.sync.aligned.m16n8k8.row.col.f32.tf32.tf32.f32 "
        "{%0,%1,%2,%3}, {%4,%5,%6,%7}, {%8,%9}, {%0,%1,%2,%3};"
        : "+f"(c[0]), "+f"(c[1]), "+f"(c[2]), "+f"(c[3])
        : "r"(a[0]), "r"(a[1]), "r"(a[2]), "r"(a[3]), "r"(b[0]), "r"(b[1]));
}

// ---------------------------------------------------------------------------
// Kernel 1: QKV projection GEMM on tf32 tensor cores (3xTF32). (unchanged R3)
// ---------------------------------------------------------------------------
__global__ __launch_bounds__(256) void qkv_gemm(
    const float* __restrict__ x,
    const float* __restrict__ Wq,
    const float* __restrict__ Wk,
    const float* __restrict__ Wv)
{
    __shared__ float As[2][16][132];   // k-major A, padded rows
    __shared__ float Bs[2][16][128];   // k-major B

    const int bz = blockIdx.z;
    const float* W = (bz == 0) ? Wq : (bz == 1 ? Wk : Wv);
    float* O = (bz == 0) ? g_q : (bz == 1 ? g_k : g_v);

    const int row0 = blockIdx.x * 128;
    const int col0 = blockIdx.y * 128;
    const int tid  = threadIdx.x;
    const int warp = tid >> 5;
    const int lane = tid & 31;
    const int wm   = (warp >> 2) * 64;   // 0 or 64
    const int wn   = (warp & 3) * 32;    // 0,32,64,96
    const int grp  = lane >> 2;          // 0..7
    const int tig  = lane & 3;           // 0..3

    const int ar = tid >> 1;            // 0..127 A row
    const int ak = (tid & 1) * 8;       // 0 or 8 A k-offset
    const int br = tid >> 5;            // 0..7   B k-row
    const int bc = (tid & 31) * 4;      // 0..124 B col

    const float* xp = x + (size_t)(row0 + ar) * D_ + ak;
    const float* wp = W + (size_t)br * NKH_ + col0 + bc;

    float acc[4][4][4];
    #pragma unroll
    for (int i = 0; i < 4; i++)
        #pragma unroll
        for (int j = 0; j < 4; j++)
            #pragma unroll
            for (int r = 0; r < 4; r++) acc[i][j][r] = 0.f;

    float4 a0 = *(const float4*)(xp);
    float4 a1 = *(const float4*)(xp + 4);
    float4 w0 = *(const float4*)(wp);
    float4 w1 = *(const float4*)(wp + (size_t)8 * NKH_);
    As[0][ak + 0][ar] = a0.x; As[0][ak + 1][ar] = a0.y;
    As[0][ak + 2][ar] = a0.z; As[0][ak + 3][ar] = a0.w;
    As[0][ak + 4][ar] = a1.x; As[0][ak + 5][ar] = a1.y;
    As[0][ak + 6][ar] = a1.z; As[0][ak + 7][ar] = a1.w;
    *(float4*)&Bs[0][br][bc]     = w0;
    *(float4*)&Bs[0][br + 8][bc] = w1;
    __syncthreads();

    int cur = 0;
    for (int k0 = 16; k0 <= D_; k0 += 16) {
        if (k0 < D_) {
            a0 = *(const float4*)(xp + k0);
            a1 = *(const float4*)(xp + k0 + 4);
            w0 = *(const float4*)(wp + (size_t)k0 * NKH_);
            w1 = *(const float4*)(wp + (size_t)(k0 + 8) * NKH_);
        }

        #pragma unroll
        for (int ka = 0; ka < 16; ka += 8) {
            const int kr0 = ka + tig;
            const int kr1 = kr0 + 4;
            unsigned ahi[4][4], alo[4][4], bhi[4][2], blo[4][2];
            #pragma unroll
            for (int i = 0; i < 4; i++) {
                const int m0 = wm + i * 16 + grp;
                tf32_split(As[cur][kr0][m0],     ahi[i][0], alo[i][0]);
                tf32_split(As[cur][kr0][m0 + 8], ahi[i][1], alo[i][1]);
                tf32_split(As[cur][kr1][m0],     ahi[i][2], alo[i][2]);
                tf32_split(As[cur][kr1][m0 + 8], ahi[i][3], alo[i][3]);
            }
            #pragma unroll
            for (int j = 0; j < 4; j++) {
                const int n0 = wn + j * 8 + grp;
                tf32_split(Bs[cur][kr0][n0], bhi[j][0], blo[j][0]);
                tf32_split(Bs[cur][kr1][n0], bhi[j][1], blo[j][1]);
            }
            #pragma unroll
            for (int i = 0; i < 4; i++)
                #pragma unroll
                for (int j = 0; j < 4; j++) {
                    mma_tf32(acc[i][j], ahi[i], bhi[j]);
                    mma_tf32(acc[i][j], ahi[i], blo[j]);
                    mma_tf32(acc[i][j], alo[i], bhi[j]);
                }
        }

        if (k0 < D_) {
            const int nxt = cur ^ 1;
            As[nxt][ak + 0][ar] = a0.x; As[nxt][ak + 1][ar] = a0.y;
            As[nxt][ak + 2][ar] = a0.z; As[nxt][ak + 3][ar] = a0.w;
            As[nxt][ak + 4][ar] = a1.x; As[nxt][ak + 5][ar] = a1.y;
            As[nxt][ak + 6][ar] = a1.z; As[nxt][ak + 7][ar] = a1.w;
            *(float4*)&Bs[nxt][br][bc]     = w0;
            *(float4*)&Bs[nxt][br + 8][bc] = w1;
            __syncthreads();
            cur = nxt;
        }
    }

    #pragma unroll
    for (int i = 0; i < 4; i++) {
        #pragma unroll
        for (int j = 0; j < 4; j++) {
            #pragma unroll
            for (int r = 0; r < 4; r++) {
                const int mrow = wm + i * 16 + grp + ((r >= 2) ? 8 : 0);
                const int ncol = wn + j * 8 + 2 * tig + (r & 1);
                const int rr = row0 + mrow;
                const int bb = rr >> 11;          // / S_
                const int s  = rr & (S_ - 1);
                const int c  = col0 + ncol;
                const int k  = c >> 4;            // / H_
                const int h  = c & (H_ - 1);
                O[((size_t)((bb * H_ + h) * S_ + s)) * KS_ + k] = acc[i][j][r];
            }
        }
    }
}

// ---------------------------------------------------------------------------
// Kernel 2: causal flash attention on tf32 tensor cores.
// One (b,h) x 64 queries per CTA; 4 warps x 16 query rows.
// 64-key K/V tiles in smem (tf32-converted at staging).
// QK^T: 1x tf32. PV: 2xTF32 (P split, V hi).
// Smem pads: K stride 68 (banks 4g+t, conflict-free B-frag loads),
//            V stride 72 (banks 8t+g, conflict-free B-frag loads).
// ---------------------------------------------------------------------------
#define KSTR 68
#define VSTR 72
__global__ __launch_bounds__(128) void attn_mma()
{
    __shared__ float Ks[64][KSTR];   // 17.0 KB
    __shared__ float Vs[64][VSTR];   // 18.0 KB

    const int bh = blockIdx.x;                       // 0..31
    const int qt = (S_ / 64 - 1) - blockIdx.y;       // heavy tiles first
    const int i0 = qt * 64;
    const int tid  = threadIdx.x;
    const int warp = tid >> 5;
    const int lane = tid & 31;
    const int g = lane >> 2;   // 0..7
    const int t = lane & 3;    // 0..3

    const float* qb = g_q + (size_t)bh * S_ * KS_;
    const float* kb = g_k + (size_t)bh * S_ * KS_;
    const float* vb = g_v + (size_t)bh * S_ * KS_;

    // Q fragments (1x tf32), scale 1/8 folded in. Warp owns rows qr..qr+15.
    const int qr = i0 + warp * 16;
    unsigned qf[8][4];
    #pragma unroll
    for (int ka = 0; ka < 8; ka++) {
        qf[ka][0] = f2tf32(qb[(size_t)(qr + g)     * KS_ + ka * 8 + t]     * 0.125f);
        qf[ka][1] = f2tf32(qb[(size_t)(qr + g + 8) * KS_ + ka * 8 + t]     * 0.125f);
        qf[ka][2] = f2tf32(qb[(size_t)(qr + g)     * KS_ + ka * 8 + t + 4] * 0.125f);
        qf[ka][3] = f2tf32(qb[(size_t)(qr + g + 8) * KS_ + ka * 8 + t + 4] * 0.125f);
    }

    float acc[8][4];
    #pragma unroll
    for (int n = 0; n < 8; n++)
        #pragma unroll
        for (int r = 0; r < 4; r++) acc[n][r] = 0.f;
    float m0 = -1e30f, m1 = -1e30f, l0 = 0.f, l1 = 0.f;

    for (int j0 = 0; j0 <= i0; j0 += 64) {
        // ---- stage K/V tile (tf32-converted once) ----
        __syncthreads();
        const float4* kt = (const float4*)(kb + (size_t)j0 * KS_);
        const float4* vt = (const float4*)(vb + (size_t)j0 * KS_);
        #pragma unroll
        for (int u = 0; u < 8; u++) {
            const int f = tid + u * 128;     // 0..1023 float4s
            const int key = f >> 4;
            const int d4  = (f & 15) * 4;
            float4 kv = kt[f];
            float4 vv = vt[f];
            float4 ko = make_float4(tf32f(kv.x), tf32f(kv.y), tf32f(kv.z), tf32f(kv.w));
            float4 vo = make_float4(tf32f(vv.x), tf32f(vv.y), tf32f(vv.z), tf32f(vv.w));
            *(float4*)&Ks[key][d4] = ko;
            *(float4*)&Vs[key][d4] = vo;
        }
        __syncthreads();

        // ---- scores: S(16x64) = Q K^T ----
        float c[8][4];
        #pragma unroll
        for (int n = 0; n < 8; n++)
            #pragma unroll
            for (int r = 0; r < 4; r++) c[n][r] = 0.f;

        #pragma unroll
        for (int ka = 0; ka < 8; ka++) {
            #pragma unroll
            for (int n = 0; n < 8; n++) {
                unsigned b[2];
                b[0] = __float_as_uint(Ks[n * 8 + g][ka * 8 + t]);
                b[1] = __float_as_uint(Ks[n * 8 + g][ka * 8 + t + 4]);
                mma_tf32(c[n], qf[ka], b);
            }
        }

        // ---- causal mask (diagonal tile only) ----
        if (j0 == i0) {
            const int r0 = qr + g;
            const int r1 = r0 + 8;
            #pragma unroll
            for (int n = 0; n < 8; n++) {
                const int k0c = j0 + n * 8 + 2 * t;
                if (k0c     > r0) c[n][0] = -1e30f;
                if (k0c + 1 > r0) c[n][1] = -1e30f;
                if (k0c     > r1) c[n][2] = -1e30f;
                if (k0c + 1 > r1) c[n][3] = -1e30f;
            }
        }

        // ---- online softmax (rows g and g+8) ----
        float t0 = -1e30f, t1 = -1e30f;
        #pragma unroll
        for (int n = 0; n < 8; n++) {
            t0 = fmaxf(t0, fmaxf(c[n][0], c[n][1]));
            t1 = fmaxf(t1, fmaxf(c[n][2], c[n][3]));
        }
        t0 = fmaxf(t0, __shfl_xor_sync(0xffffffffu, t0, 1));
        t0 = fmaxf(t0, __shfl_xor_sync(0xffffffffu, t0, 2));
        t1 = fmaxf(t1, __shfl_xor_sync(0xffffffffu, t1, 1));
        t1 = fmaxf(t1, __shfl_xor_sync(0xffffffffu, t1, 2));
        const float nm0 = fmaxf(m0, t0);
        const float nm1 = fmaxf(m1, t1);
        const float f0 = __expf(m0 - nm0);
        const float f1 = __expf(m1 - nm1);
        m0 = nm0; m1 = nm1;
        l0 *= f0;  l1 *= f1;
        #pragma unroll
        for (int n = 0; n < 8; n++) {
            acc[n][0] *= f0; acc[n][1] *= f0;
            acc[n][2] *= f1; acc[n][3] *= f1;
        }
        float ps0 = 0.f, ps1 = 0.f;
        #pragma unroll
        for (int n = 0; n < 8; n++) {
            c[n][0] = __expf(c[n][0] - m0);
            c[n][1] = __expf(c[n][1] - m0);
            c[n][2] = __expf(c[n][2] - m1);
            c[n][3] = __expf(c[n][3] - m1);
            ps0 += c[n][0] + c[n][1];
            ps1 += c[n][2] + c[n][3];
        }
        ps0 += __shfl_xor_sync(0xffffffffu, ps0, 1);
        ps0 += __shfl_xor_sync(0xffffffffu, ps0, 2);
        ps1 += __shfl_xor_sync(0xffffffffu, ps1, 1);
        ps1 += __shfl_xor_sync(0xffffffffu, ps1, 2);
        l0 += ps0; l1 += ps1;

        // ---- PV: acc += P V  (2xTF32: P split, V hi) ----
        const int srcA = g * 4 + (t >> 1);
        const int srcB = srcA + 2;
        const bool odd = (t & 1);
        #pragma unroll
        for (int ka = 0; ka < 8; ka++) {
            // gather P A-fragment via shuffles (C-layout -> A-layout)
            float w00 = __shfl_sync(0xffffffffu, c[ka][0], srcA);
            float w01 = __shfl_sync(0xffffffffu, c[ka][1], srcA);
            float w10 = __shfl_sync(0xffffffffu, c[ka][2], srcA);
            float w11 = __shfl_sync(0xffffffffu, c[ka][3], srcA);
            float x00 = __shfl_sync(0xffffffffu, c[ka][0], srcB);
            float x01 = __shfl_sync(0xffffffffu, c[ka][1], srcB);
            float x10 = __shfl_sync(0xffffffffu, c[ka][2], srcB);
            float x11 = __shfl_sync(0xffffffffu, c[ka][3], srcB);
            const float p0 = odd ? w01 : w00;   // row g,   col ka*8+t
            const float p1 = odd ? w11 : w10;   // row g+8, col ka*8+t
            const float p2 = odd ? x01 : x00;   // row g,   col ka*8+t+4
            const float p3 = odd ? x11 : x10;   // row g+8, col ka*8+t+4
            unsigned ahi[4], alo[4];
            tf32_split(p0, ahi[0], alo[0]);
            tf32_split(p1, ahi[1], alo[1]);
            tf32_split(p2, ahi[2], alo[2]);
            tf32_split(p3, ahi[3], alo[3]);
            #pragma unroll
            for (int n = 0; n < 8; n++) {
                unsigned b[2];
                b[0] = __float_as_uint(Vs[ka * 8 + t][n * 8 + g]);
                b[1] = __float_as_uint(Vs[ka * 8 + t + 4][n * 8 + g]);
                mma_tf32(acc[n], ahi, b);
                mma_tf32(acc[n], alo, b);
            }
        }
    }

    // ---- epilogue: normalize + scatter to g_heads [b,s,k*H+h] ----
    const float inv0 = 1.f / l0;
    const float inv1 = 1.f / l1;
    const int bb = bh >> 4;        // / H_
    const int h  = bh & (H_ - 1);
    const int r0 = qr + g;
    const int r1 = r0 + 8;
    float* hp0 = g_heads + ((size_t)(bb * S_ + r0)) * NKH_ + h;
    float* hp1 = g_heads + ((size_t)(bb * S_ + r1)) * NKH_ + h;
    #pragma unroll
    for (int n = 0; n < 8; n++) {
        const int k0c = n * 8 + 2 * t;
        hp0[(k0c)     * H_] = acc[n][0] * inv0;
        hp0[(k0c + 1) * H_] = acc[n][1] * inv0;
        hp1[(k0c)     * H_] = acc[n][2] * inv1;
        hp1[(k0c + 1) * H_] = acc[n][3] * inv1;
    }
}

// ---------------------------------------------------------------------------
// Kernel 3: output projection. (unchanged)
// ---------------------------------------------------------------------------
__global__ __launch_bounds__(256) void out_gemm(
    const float* __restrict__ kern,
    float* __restrict__ out)
{
    __shared__ float Hs[32][33];
    __shared__ float Ws[32][64];

    const int row0 = blockIdx.x * 32;
    const int tid  = threadIdx.x;
    const int tx   = tid & 15;
    const int ty   = tid >> 4;

    const int hr = tid >> 3;
    const int hc = (tid & 7) * 4;
    const int wr = tid >> 4;
    const int wc = (tid & 15) * 4;

    float acc[2][4];
    #pragma unroll
    for (int ii = 0; ii < 2; ii++)
        #pragma unroll
        for (int jj = 0; jj < 4; jj++) acc[ii][jj] = 0.f;

    for (int k0 = 0; k0 < NKH_; k0 += 32) {
        float4 hv = *(const float4*)(g_heads + (size_t)(row0 + hr) * NKH_ + k0 + hc);
        float4 w0 = *(const float4*)(kern + (size_t)(k0 + wr) * KS_ + wc);
        float4 w1 = *(const float4*)(kern + (size_t)(k0 + wr + 16) * KS_ + wc);
        __syncthreads();
        Hs[hc + 0][hr] = hv.x;
        Hs[hc + 1][hr] = hv.y;
        Hs[hc + 2][hr] = hv.z;
        Hs[hc + 3][hr] = hv.w;
        *(float4*)&Ws[wr][wc]      = w0;
        *(float4*)&Ws[wr + 16][wc] = w1;
        __syncthreads();

        #pragma unroll
        for (int kk = 0; kk < 32; kk++) {
            const float a0 = Hs[kk][ty * 2 + 0];
            const float a1 = Hs[kk][ty * 2 + 1];
            const float b0 = Ws[kk][tx * 4 + 0];
            const float b1 = Ws[kk][tx * 4 + 1];
            const float b2 = Ws[kk][tx * 4 + 2];
            const float b3 = Ws[kk][tx * 4 + 3];
            acc[0][0] = fmaf(a0, b0, acc[0][0]);
            acc[0][1] = fmaf(a0, b1, acc[0][1]);
            acc[0][2] = fmaf(a0, b2, acc[0][2]);
            acc[0][3] = fmaf(a0, b3, acc[0][3]);
            acc[1][0] = fmaf(a1, b0, acc[1][0]);
            acc[1][1] = fmaf(a1, b1, acc[1][1]);
            acc[1][2] = fmaf(a1, b2, acc[1][2]);
            acc[1][3] = fmaf(a1, b3, acc[1][3]);
        }
    }

    #pragma unroll
    for (int ii = 0; ii < 2; ii++) {
        float4 o = make_float4(acc[ii][0], acc[ii][1], acc[ii][2], acc[ii][3]);
        *(float4*)(out + (size_t)(row0 + ty * 2 + ii) * KS_ + tx * 4) = o;
    }
}

// ---------------------------------------------------------------------------
extern "C" void kernel_launch(void* const* d_in, const int* in_sizes, int n_in,
                              void* d_out, int out_size)
{
    (void)in_sizes; (void)n_in; (void)out_size;
    const float* x  = (const float*)d_in[0];
    const float* Wq = (const float*)d_in[1];
    const float* Wk = (const float*)d_in[2];
    const float* Wv = (const float*)d_in[3];
    const float* kr = (const float*)d_in[4];
    float* out = (float*)d_out;

    dim3 g1(B_ * S_ / 128, NKH_ / 128, 3);   // (32, 8, 3)
    qkv_gemm<<<g1, 256>>>(x, Wq, Wk, Wv);

    dim3 g2(NBH_, S_ / 64);                  // (32, 32)
    attn_mma<<<g2, 128>>>();

    out_gemm<<<B_ * S_ / 32, 256>>>(kr, out); // 128 blocks
}

// round 5
// speedup vs baseline: 2.1378x; 1.0060x over previous
#include <cuda_runtime.h>

// Problem dims (fixed)
#define B_   2
#define S_   2048
#define D_   1024
#define H_   16
#define KS_  64
#define NKH_ (KS_ * H_)   // 1024
#define NBH_ (B_ * H_)    // 32

// Device scratch (allocation-free rule: device globals)
__device__ float g_q[NBH_ * S_ * KS_];      // [b,h,s,k]
__device__ float g_k[NBH_ * S_ * KS_];
__device__ float g_v[NBH_ * S_ * KS_];
__device__ float g_heads[B_ * S_ * NKH_];   // [b,s, k*H+h]

// ---------------------------------------------------------------------------
// TF32 helpers
// ---------------------------------------------------------------------------
__device__ __forceinline__ unsigned f2tf32(float f) {
    unsigned r;
    asm("cvt.rna.tf32.f32 %0, %1;" : "=r"(r) : "f"(f));
    return r;
}
__device__ __forceinline__ float tf32f(float f) {
    return __uint_as_float(f2tf32(f));
}
__device__ __forceinline__ void tf32_split(float f, unsigned& hi, unsigned& lo) {
    hi = f2tf32(f);
    lo = f2tf32(f - __uint_as_float(hi));
}
// (hi, lo) both tf32-rounded, packed as float2 for smem staging
__device__ __forceinline__ float2 split2(float f) {
    unsigned hi = f2tf32(f);
    float lo = tf32f(f - __uint_as_float(hi));
    return make_float2(__uint_as_float(hi), lo);
}
__device__ __forceinline__ void mma_tf32(float* c, const unsigned* a, const unsigned* b) {
    asm volatile(
        "mma.sync.aligned.m16n8k8.row.col.f32.tf32.tf32.f32 "
        "{%0,%1,%2,%3}, {%4,%5,%6,%7}, {%8,%9}, {%0,%1,%2,%3};"
        : "+f"(c[0]), "+f"(c[1]), "+f"(c[2]), "+f"(c[3])
        : "r"(a[0]), "r"(a[1]), "r"(a[2]), "r"(a[3]), "r"(b[0]), "r"(b[1]));
}

// ---------------------------------------------------------------------------
// Kernel 1: QKV projection GEMM, 3xTF32, split-at-staging.
// C[4096][1024] = X[4096][1024] * W[1024][1024].
// BM=128, BN=128, BK=8, 256 threads = 8 warps (2x4), warp tile 64x32.
// Smem holds (hi,lo) tf32 pairs; inner loop is pure LDS + MMA.
// Row stride 132 float2 => fragment LDS.64 banks (2g+8t) conflict-free.
// ---------------------------------------------------------------------------
__global__ __launch_bounds__(256) void qkv_gemm(
    const float* __restrict__ x,
    const float* __restrict__ Wq,
    const float* __restrict__ Wk,
    const float* __restrict__ Wv)
{
    __shared__ float2 As2[2][8][132];   // [k][m] (hi,lo), 16.9 KB
    __shared__ float2 Bs2[2][8][132];   // [k][n] (hi,lo), 16.9 KB

    const int bz = blockIdx.z;
    const float* W = (bz == 0) ? Wq : (bz == 1 ? Wk : Wv);
    float* O = (bz == 0) ? g_q : (bz == 1 ? g_k : g_v);

    const int row0 = blockIdx.x * 128;
    const int col0 = blockIdx.y * 128;
    const int tid  = threadIdx.x;
    const int warp = tid >> 5;
    const int lane = tid & 31;
    const int wm   = (warp >> 2) * 64;   // 0 or 64
    const int wn   = (warp & 3) * 32;    // 0,32,64,96
    const int g    = lane >> 2;          // 0..7
    const int t    = lane & 3;           // 0..3

    // Staging indices: A 128 rows x 8 k, B 8 k x 128 cols
    const int ar = tid >> 1;            // 0..127 A row
    const int ak = (tid & 1) * 4;       // 0 or 4 A k-offset
    const int br = tid >> 5;            // 0..7   B k-row
    const int bc = (tid & 31) * 4;      // 0..124 B col

    const float* xp = x + (size_t)(row0 + ar) * D_ + ak;
    const float* wp = W + (size_t)br * NKH_ + col0 + bc;

    float acc[4][4][4];
    #pragma unroll
    for (int i = 0; i < 4; i++)
        #pragma unroll
        for (int j = 0; j < 4; j++)
            #pragma unroll
            for (int r = 0; r < 4; r++) acc[i][j][r] = 0.f;

    // Preload k-tile 0 into buffer 0 (split at staging)
    float4 av = *(const float4*)(xp);
    float4 wv = *(const float4*)(wp);
    As2[0][ak + 0][ar] = split2(av.x);
    As2[0][ak + 1][ar] = split2(av.y);
    As2[0][ak + 2][ar] = split2(av.z);
    As2[0][ak + 3][ar] = split2(av.w);
    Bs2[0][br][bc + 0] = split2(wv.x);
    Bs2[0][br][bc + 1] = split2(wv.y);
    Bs2[0][br][bc + 2] = split2(wv.z);
    Bs2[0][br][bc + 3] = split2(wv.w);
    __syncthreads();

    int cur = 0;
    #pragma unroll 1
    for (int k0 = 8; k0 <= D_; k0 += 8) {
        // Prefetch next k-tile into registers
        if (k0 < D_) {
            av = *(const float4*)(xp + k0);
            wv = *(const float4*)(wp + (size_t)k0 * NKH_);
        }

        // Compute on current buffer: one k8 atom, pure LDS + MMA
        unsigned ahi[4][4], alo[4][4], bhi[4][2], blo[4][2];
        #pragma unroll
        for (int i = 0; i < 4; i++) {
            const int m0 = wm + i * 16 + g;
            float2 p0 = As2[cur][t][m0];
            float2 p1 = As2[cur][t][m0 + 8];
            float2 p2 = As2[cur][t + 4][m0];
            float2 p3 = As2[cur][t + 4][m0 + 8];
            ahi[i][0] = __float_as_uint(p0.x); alo[i][0] = __float_as_uint(p0.y);
            ahi[i][1] = __float_as_uint(p1.x); alo[i][1] = __float_as_uint(p1.y);
            ahi[i][2] = __float_as_uint(p2.x); alo[i][2] = __float_as_uint(p2.y);
            ahi[i][3] = __float_as_uint(p3.x); alo[i][3] = __float_as_uint(p3.y);
        }
        #pragma unroll
        for (int j = 0; j < 4; j++) {
            const int n0 = wn + j * 8 + g;
            float2 q0 = Bs2[cur][t][n0];
            float2 q1 = Bs2[cur][t + 4][n0];
            bhi[j][0] = __float_as_uint(q0.x); blo[j][0] = __float_as_uint(q0.y);
            bhi[j][1] = __float_as_uint(q1.x); blo[j][1] = __float_as_uint(q1.y);
        }
        #pragma unroll
        for (int i = 0; i < 4; i++)
            #pragma unroll
            for (int j = 0; j < 4; j++) {
                mma_tf32(acc[i][j], ahi[i], bhi[j]);
                mma_tf32(acc[i][j], ahi[i], blo[j]);
                mma_tf32(acc[i][j], alo[i], bhi[j]);
            }

        if (k0 < D_) {
            const int nxt = cur ^ 1;
            As2[nxt][ak + 0][ar] = split2(av.x);
            As2[nxt][ak + 1][ar] = split2(av.y);
            As2[nxt][ak + 2][ar] = split2(av.z);
            As2[nxt][ak + 3][ar] = split2(av.w);
            Bs2[nxt][br][bc + 0] = split2(wv.x);
            Bs2[nxt][br][bc + 1] = split2(wv.y);
            Bs2[nxt][br][bc + 2] = split2(wv.z);
            Bs2[nxt][br][bc + 3] = split2(wv.w);
            __syncthreads();
            cur = nxt;
        }
    }

    // Epilogue: scatter to [b,h,s,k]
    #pragma unroll
    for (int i = 0; i < 4; i++) {
        #pragma unroll
        for (int j = 0; j < 4; j++) {
            #pragma unroll
            for (int r = 0; r < 4; r++) {
                const int mrow = wm + i * 16 + g + ((r >= 2) ? 8 : 0);
                const int ncol = wn + j * 8 + 2 * t + (r & 1);
                const int rr = row0 + mrow;
                const int bb = rr >> 11;          // / S_
                const int s  = rr & (S_ - 1);
                const int c  = col0 + ncol;
                const int k  = c >> 4;            // / H_
                const int h  = c & (H_ - 1);
                O[((size_t)((bb * H_ + h) * S_ + s)) * KS_ + k] = acc[i][j][r];
            }
        }
    }
}

// ---------------------------------------------------------------------------
// Kernel 2: causal flash attention on tf32 tensor cores. (unchanged R4)
// ---------------------------------------------------------------------------
#define KSTR 68
#define VSTR 72
__global__ __launch_bounds__(128) void attn_mma()
{
    __shared__ float Ks[64][KSTR];   // 17.0 KB
    __shared__ float Vs[64][VSTR];   // 18.0 KB

    const int bh = blockIdx.x;                       // 0..31
    const int qt = (S_ / 64 - 1) - blockIdx.y;       // heavy tiles first
    const int i0 = qt * 64;
    const int tid  = threadIdx.x;
    const int warp = tid >> 5;
    const int lane = tid & 31;
    const int g = lane >> 2;   // 0..7
    const int t = lane & 3;    // 0..3

    const float* qb = g_q + (size_t)bh * S_ * KS_;
    const float* kb = g_k + (size_t)bh * S_ * KS_;
    const float* vb = g_v + (size_t)bh * S_ * KS_;

    const int qr = i0 + warp * 16;
    unsigned qf[8][4];
    #pragma unroll
    for (int ka = 0; ka < 8; ka++) {
        qf[ka][0] = f2tf32(qb[(size_t)(qr + g)     * KS_ + ka * 8 + t]     * 0.125f);
        qf[ka][1] = f2tf32(qb[(size_t)(qr + g + 8) * KS_ + ka * 8 + t]     * 0.125f);
        qf[ka][2] = f2tf32(qb[(size_t)(qr + g)     * KS_ + ka * 8 + t + 4] * 0.125f);
        qf[ka][3] = f2tf32(qb[(size_t)(qr + g + 8) * KS_ + ka * 8 + t + 4] * 0.125f);
    }

    float acc[8][4];
    #pragma unroll
    for (int n = 0; n < 8; n++)
        #pragma unroll
        for (int r = 0; r < 4; r++) acc[n][r] = 0.f;
    float m0 = -1e30f, m1 = -1e30f, l0 = 0.f, l1 = 0.f;

    for (int j0 = 0; j0 <= i0; j0 += 64) {
        __syncthreads();
        const float4* kt = (const float4*)(kb + (size_t)j0 * KS_);
        const float4* vt = (const float4*)(vb + (size_t)j0 * KS_);
        #pragma unroll
        for (int u = 0; u < 8; u++) {
            const int f = tid + u * 128;     // 0..1023 float4s
            const int key = f >> 4;
            const int d4  = (f & 15) * 4;
            float4 kv = kt[f];
            float4 vv = vt[f];
            float4 ko = make_float4(tf32f(kv.x), tf32f(kv.y), tf32f(kv.z), tf32f(kv.w));
            float4 vo = make_float4(tf32f(vv.x), tf32f(vv.y), tf32f(vv.z), tf32f(vv.w));
            *(float4*)&Ks[key][d4] = ko;
            *(float4*)&Vs[key][d4] = vo;
        }
        __syncthreads();

        float c[8][4];
        #pragma unroll
        for (int n = 0; n < 8; n++)
            #pragma unroll
            for (int r = 0; r < 4; r++) c[n][r] = 0.f;

        #pragma unroll
        for (int ka = 0; ka < 8; ka++) {
            #pragma unroll
            for (int n = 0; n < 8; n++) {
                unsigned b[2];
                b[0] = __float_as_uint(Ks[n * 8 + g][ka * 8 + t]);
                b[1] = __float_as_uint(Ks[n * 8 + g][ka * 8 + t + 4]);
                mma_tf32(c[n], qf[ka], b);
            }
        }

        if (j0 == i0) {
            const int r0 = qr + g;
            const int r1 = r0 + 8;
            #pragma unroll
            for (int n = 0; n < 8; n++) {
                const int k0c = j0 + n * 8 + 2 * t;
                if (k0c     > r0) c[n][0] = -1e30f;
                if (k0c + 1 > r0) c[n][1] = -1e30f;
                if (k0c     > r1) c[n][2] = -1e30f;
                if (k0c + 1 > r1) c[n][3] = -1e30f;
            }
        }

        float t0 = -1e30f, t1 = -1e30f;
        #pragma unroll
        for (int n = 0; n < 8; n++) {
            t0 = fmaxf(t0, fmaxf(c[n][0], c[n][1]));
            t1 = fmaxf(t1, fmaxf(c[n][2], c[n][3]));
        }
        t0 = fmaxf(t0, __shfl_xor_sync(0xffffffffu, t0, 1));
        t0 = fmaxf(t0, __shfl_xor_sync(0xffffffffu, t0, 2));
        t1 = fmaxf(t1, __shfl_xor_sync(0xffffffffu, t1, 1));
        t1 = fmaxf(t1, __shfl_xor_sync(0xffffffffu, t1, 2));
        const float nm0 = fmaxf(m0, t0);
        const float nm1 = fmaxf(m1, t1);
        const float f0 = __expf(m0 - nm0);
        const float f1 = __expf(m1 - nm1);
        m0 = nm0; m1 = nm1;
        l0 *= f0;  l1 *= f1;
        #pragma unroll
        for (int n = 0; n < 8; n++) {
            acc[n][0] *= f0; acc[n][1] *= f0;
            acc[n][2] *= f1; acc[n][3] *= f1;
        }
        float ps0 = 0.f, ps1 = 0.f;
        #pragma unroll
        for (int n = 0; n < 8; n++) {
            c[n][0] = __expf(c[n][0] - m0);
            c[n][1] = __expf(c[n][1] - m0);
            c[n][2] = __expf(c[n][2] - m1);
            c[n][3] = __expf(c[n][3] - m1);
            ps0 += c[n][0] + c[n][1];
            ps1 += c[n][2] + c[n][3];
        }
        ps0 += __shfl_xor_sync(0xffffffffu, ps0, 1);
        ps0 += __shfl_xor_sync(0xffffffffu, ps0, 2);
        ps1 += __shfl_xor_sync(0xffffffffu, ps1, 1);
        ps1 += __shfl_xor_sync(0xffffffffu, ps1, 2);
        l0 += ps0; l1 += ps1;

        const int srcA = g * 4 + (t >> 1);
        const int srcB = srcA + 2;
        const bool odd = (t & 1);
        #pragma unroll
        for (int ka = 0; ka < 8; ka++) {
            float w00 = __shfl_sync(0xffffffffu, c[ka][0], srcA);
            float w01 = __shfl_sync(0xffffffffu, c[ka][1], srcA);
            float w10 = __shfl_sync(0xffffffffu, c[ka][2], srcA);
            float w11 = __shfl_sync(0xffffffffu, c[ka][3], srcA);
            float x00 = __shfl_sync(0xffffffffu, c[ka][0], srcB);
            float x01 = __shfl_sync(0xffffffffu, c[ka][1], srcB);
            float x10 = __shfl_sync(0xffffffffu, c[ka][2], srcB);
            float x11 = __shfl_sync(0xffffffffu, c[ka][3], srcB);
            const float p0 = odd ? w01 : w00;
            const float p1 = odd ? w11 : w10;
            const float p2 = odd ? x01 : x00;
            const float p3 = odd ? x11 : x10;
            unsigned ahi[4], alo[4];
            tf32_split(p0, ahi[0], alo[0]);
            tf32_split(p1, ahi[1], alo[1]);
            tf32_split(p2, ahi[2], alo[2]);
            tf32_split(p3, ahi[3], alo[3]);
            #pragma unroll
            for (int n = 0; n < 8; n++) {
                unsigned b[2];
                b[0] = __float_as_uint(Vs[ka * 8 + t][n * 8 + g]);
                b[1] = __float_as_uint(Vs[ka * 8 + t + 4][n * 8 + g]);
                mma_tf32(acc[n], ahi, b);
                mma_tf32(acc[n], alo, b);
            }
        }
    }

    const float inv0 = 1.f / l0;
    const float inv1 = 1.f / l1;
    const int bb = bh >> 4;        // / H_
    const int h  = bh & (H_ - 1);
    const int r0 = qr + g;
    const int r1 = r0 + 8;
    float* hp0 = g_heads + ((size_t)(bb * S_ + r0)) * NKH_ + h;
    float* hp1 = g_heads + ((size_t)(bb * S_ + r1)) * NKH_ + h;
    #pragma unroll
    for (int n = 0; n < 8; n++) {
        const int k0c = n * 8 + 2 * t;
        hp0[(k0c)     * H_] = acc[n][0] * inv0;
        hp0[(k0c + 1) * H_] = acc[n][1] * inv0;
        hp1[(k0c)     * H_] = acc[n][2] * inv1;
        hp1[(k0c + 1) * H_] = acc[n][3] * inv1;
    }
}

// ---------------------------------------------------------------------------
// Kernel 3: output projection. (unchanged)
// ---------------------------------------------------------------------------
__global__ __launch_bounds__(256) void out_gemm(
    const float* __restrict__ kern,
    float* __restrict__ out)
{
    __shared__ float Hs[32][33];
    __shared__ float Ws[32][64];

    const int row0 = blockIdx.x * 32;
    const int tid  = threadIdx.x;
    const int tx   = tid & 15;
    const int ty   = tid >> 4;

    const int hr = tid >> 3;
    const int hc = (tid & 7) * 4;
    const int wr = tid >> 4;
    const int wc = (tid & 15) * 4;

    float acc[2][4];
    #pragma unroll
    for (int ii = 0; ii < 2; ii++)
        #pragma unroll
        for (int jj = 0; jj < 4; jj++) acc[ii][jj] = 0.f;

    for (int k0 = 0; k0 < NKH_; k0 += 32) {
        float4 hv = *(const float4*)(g_heads + (size_t)(row0 + hr) * NKH_ + k0 + hc);
        float4 w0 = *(const float4*)(kern + (size_t)(k0 + wr) * KS_ + wc);
        float4 w1 = *(const float4*)(kern + (size_t)(k0 + wr + 16) * KS_ + wc);
        __syncthreads();
        Hs[hc + 0][hr] = hv.x;
        Hs[hc + 1][hr] = hv.y;
        Hs[hc + 2][hr] = hv.z;
        Hs[hc + 3][hr] = hv.w;
        *(float4*)&Ws[wr][wc]      = w0;
        *(float4*)&Ws[wr + 16][wc] = w1;
        __syncthreads();

        #pragma unroll
        for (int kk = 0; kk < 32; kk++) {
            const float a0 = Hs[kk][ty * 2 + 0];
            const float a1 = Hs[kk][ty * 2 + 1];
            const float b0 = Ws[kk][tx * 4 + 0];
            const float b1 = Ws[kk][tx * 4 + 1];
            const float b2 = Ws[kk][tx * 4 + 2];
            const float b3 = Ws[kk][tx * 4 + 3];
            acc[0][0] = fmaf(a0, b0, acc[0][0]);
            acc[0][1] = fmaf(a0, b1, acc[0][1]);
            acc[0][2] = fmaf(a0, b2, acc[0][2]);
            acc[0][3] = fmaf(a0, b3, acc[0][3]);
            acc[1][0] = fmaf(a1, b0, acc[1][0]);
            acc[1][1] = fmaf(a1, b1, acc[1][1]);
            acc[1][2] = fmaf(a1, b2, acc[1][2]);
            acc[1][3] = fmaf(a1, b3, acc[1][3]);
        }
    }

    #pragma unroll
    for (int ii = 0; ii < 2; ii++) {
        float4 o = make_float4(acc[ii][0], acc[ii][1], acc[ii][2], acc[ii][3]);
        *(float4*)(out + (size_t)(row0 + ty * 2 + ii) * KS_ + tx * 4) = o;
    }
}

// ---------------------------------------------------------------------------
extern "C" void kernel_launch(void* const* d_in, const int* in_sizes, int n_in,
                              void* d_out, int out_size)
{
    (void)in_sizes; (void)n_in; (void)out_size;
    const float* x  = (const float*)d_in[0];
    const float* Wq = (const float*)d_in[1];
    const float* Wk = (const float*)d_in[2];
    const float* Wv = (const float*)d_in[3];
    const float* kr = (const float*)d_in[4];
    float* out = (float*)d_out;

    dim3 g1(B_ * S_ / 128, NKH_ / 128, 3);   // (32, 8, 3)
    qkv_gemm<<<g1, 256>>>(x, Wq, Wk, Wv);

    dim3 g2(NBH_, S_ / 64);                  // (32, 32)
    attn_mma<<<g2, 128>>>();

    out_gemm<<<B_ * S_ / 32, 256>>>(kr, out); // 128 blocks
}